// round 3
// baseline (speedup 1.0000x reference)
#include <cuda_runtime.h>
#include <math.h>

#define B_ 16
#define N_ 196
#define C_ 512
#define T_ 20
#define D_ 128
#define S_ 38
#define NP_ 224                    // padded row/col stride for chain matrices
#define MP2_ (NP_*NP_)             // 50176 floats per padded matrix
#define QSIZE 8028160              // B*D*T*N
#define INV_TEMP (1.0f/0.07f)
#define EPS_ 1e-20f

// ---------------- scratch (static device globals; no allocation) ----------------
__device__ float g_qA[B_*T_*N_*D_];                  // [b][t][n][d] normalized q
__device__ float g_P[(size_t)B_*S_*MP2_];            // padded transition mats (224x224)
__device__ float g_buf1[(size_t)B_*19*MP2_];         // tree ping
__device__ float g_buf2[(size_t)B_*10*MP2_];         // tree pong (final At at [b][0])
__device__ float g_partial[2*B_];

// =============================================================================
// Kernel A: spatial pool + linear head + L2 normalize. (unchanged)
// =============================================================================
#define SMEM_A_BYTES ((C_*T_ + 64*D_ + 32) * sizeof(float))

__global__ __launch_bounds__(128) void kA(const float* __restrict__ maps,
                                          const float* __restrict__ W,
                                          const float* __restrict__ bias,
                                          float* __restrict__ qout) {
  extern __shared__ float sm[];
  float* qp    = sm;
  float* Ws    = sm + C_*T_;
  float* inorm = Ws + 64*D_;

  const int bn  = blockIdx.x;
  const int tid = threadIdx.x;

  const float4* src = reinterpret_cast<const float4*>(maps) + (size_t)bn * (C_*T_);
  for (int i = tid; i < C_*T_; i += 128) {
    float4 v = src[i];
    qp[i] = (v.x + v.y + v.z + v.w) * 0.25f;
  }
  __syncthreads();

  const int d0 = (tid & 31) * 4;
  const int t0 = (tid >> 5) * 5;
  float acc[4][5];
#pragma unroll
  for (int a = 0; a < 4; ++a)
#pragma unroll
    for (int t = 0; t < 5; ++t) acc[a][t] = 0.f;

  for (int cc = 0; cc < C_; cc += 64) {
    __syncthreads();
    const float4* wg  = reinterpret_cast<const float4*>(W + (size_t)cc * D_);
    float4*       ws4 = reinterpret_cast<float4*>(Ws);
    for (int j = tid; j < 64*D_/4; j += 128) ws4[j] = wg[j];
    __syncthreads();
#pragma unroll 4
    for (int k = 0; k < 64; ++k) {
      const int c = cc + k;
      float4 w = *reinterpret_cast<const float4*>(&Ws[k*D_ + d0]);
      float qv[5];
#pragma unroll
      for (int t = 0; t < 5; ++t) qv[t] = qp[c*T_ + t0 + t];
#pragma unroll
      for (int t = 0; t < 5; ++t) {
        acc[0][t] += w.x * qv[t];
        acc[1][t] += w.y * qv[t];
        acc[2][t] += w.z * qv[t];
        acc[3][t] += w.w * qv[t];
      }
    }
  }
  __syncthreads();

  float4 bv4 = *reinterpret_cast<const float4*>(bias + d0);
  float bvv[4] = {bv4.x, bv4.y, bv4.z, bv4.w};

  float part[5];
#pragma unroll
  for (int t = 0; t < 5; ++t) {
    float p = 0.f;
#pragma unroll
    for (int dd = 0; dd < 4; ++dd) {
      float yv = acc[dd][t] + bvv[dd];
      qp[(t0 + t)*D_ + (d0 + dd)] = yv;
      p += yv * yv;
    }
    part[t] = p;
  }
  float* red = Ws;
#pragma unroll
  for (int t = 0; t < 5; ++t) red[(t0 + t)*32 + (tid & 31)] = part[t];
  __syncthreads();

  if (tid < T_) {
    float ss = 0.f;
#pragma unroll
    for (int j = 0; j < 32; ++j) ss += red[tid*32 + j];
    inorm[tid] = 1.0f / fmaxf(sqrtf(ss), 1e-12f);
  }
  __syncthreads();

  const int b = bn / N_;
  const int n = bn % N_;
  for (int i = tid; i < T_*D_; i += 128) {
    const int t = i >> 7, d = i & 127;
    float v = qp[t*D_ + d] * inorm[t];
    g_qA[((size_t)(b*T_ + t)*N_ + n)*D_ + d] = v;
    qout[((size_t)(b*D_ + d)*T_ + t)*N_ + n] = v;
  }
}

// =============================================================================
// Kernel B: affinity + palindrome softmax -> padded P (224x224, pad zeroed).
// =============================================================================
#define SMEM_B_BYTES ((N_*197 + 2*16*N_) * sizeof(float))

__global__ __launch_bounds__(392) void kB() {
  extern __shared__ float sm[];
  float* Sm = sm;                    // 196 x 197
  float* Qa = sm + N_*197;           // 16 x 196
  float* Qb = Qa + 16*N_;            // 16 x 196

  const int t   = blockIdx.x;
  const int b   = blockIdx.y;
  const int tid = threadIdx.x;
  const int ty  = tid / 14, tx = tid % 14;
  const int r0  = ty * 7,   c0 = tx * 14;

  const float* qa_base = g_qA + (size_t)((b*T_ + t    )*N_) * D_;
  const float* qb_base = g_qA + (size_t)((b*T_ + t + 1)*N_) * D_;

  float acc[7][14];
#pragma unroll
  for (int i = 0; i < 7; ++i)
#pragma unroll
    for (int j = 0; j < 14; ++j) acc[i][j] = 0.f;

  for (int k0 = 0; k0 < D_; k0 += 16) {
    __syncthreads();
    for (int idx = tid; idx < N_*16; idx += 392) {
      const int n = idx >> 4, k = idx & 15;
      Qa[k*N_ + n] = qa_base[(size_t)n*D_ + k0 + k];
      Qb[k*N_ + n] = qb_base[(size_t)n*D_ + k0 + k];
    }
    __syncthreads();
#pragma unroll
    for (int k = 0; k < 16; ++k) {
      float ra[7], rb[14];
#pragma unroll
      for (int i = 0; i < 7; ++i)  ra[i] = Qa[k*N_ + r0 + i];
#pragma unroll
      for (int j = 0; j < 14; ++j) rb[j] = Qb[k*N_ + c0 + j];
#pragma unroll
      for (int i = 0; i < 7; ++i)
#pragma unroll
        for (int j = 0; j < 14; ++j) acc[i][j] += ra[i] * rb[j];
    }
  }
  __syncthreads();

#pragma unroll
  for (int i = 0; i < 7; ++i)
#pragma unroll
    for (int j = 0; j < 14; ++j)
      Sm[(r0 + i)*197 + (c0 + j)] = acc[i][j] * INV_TEMP;
  __syncthreads();

  for (int idx = tid; idx < N_*N_; idx += 392) {
    const int rr = idx / N_, mm = idx - rr*N_;
    Sm[rr*197 + mm] = __expf(Sm[rr*197 + mm]);
  }
  __syncthreads();

  float* rinv = Qa;
  float* cinv = Qa + N_;
  if (tid < N_) {
    float rs = 0.f, cs = 0.f;
    for (int m = 0; m < N_; ++m) {
      rs += Sm[tid*197 + m];
      cs += Sm[m*197 + tid];
    }
    rinv[tid] = 1.0f / rs;
    cinv[tid] = 1.0f / cs;
  }
  __syncthreads();

  float* Pf = g_P + (size_t)(b*S_ + t       )*MP2_;
  float* Pb = g_P + (size_t)(b*S_ + (37 - t))*MP2_;
  for (int idx = tid; idx < MP2_; idx += 392) {
    const int rr = idx / NP_, mm = idx - rr*NP_;
    float vf = 0.f, vb = 0.f;
    if (rr < N_ && mm < N_) {
      vf = Sm[rr*197 + mm] * rinv[rr];
      vb = Sm[mm*197 + rr] * cinv[rr];
    }
    Pf[idx] = vf;
    Pb[idx] = vb;
  }
}

// =============================================================================
// Kernel C v3: product-tree GEMM on tensor cores (mma.sync m16n8k8 tf32),
// fp32-split precision: x = hi + lo; C += Ah*Bh + Ah*Bl + Al*Bh.
// Matrices 224x224 padded (zeros propagate). CTA tile 112x112, 224 thr (7
// warps), warp = one 16-row band x 112 cols (14 n-tiles). K chunk 32.
// =============================================================================
#define KCH_ 32
#define SSTR_ 113                                 // smem stride (conflict-free)
#define SMEM_C_FLOATS (4 * KCH_ * SSTR_)          // AsH, AsL, BsH, BsL
#define SMEM_C_BYTES  (SMEM_C_FLOATS * sizeof(float))

__device__ __forceinline__ unsigned f2tf32(float x) {
  unsigned r;
  asm("cvt.rna.tf32.f32 %0, %1;" : "=r"(r) : "f"(x));
  return r;
}

__device__ __forceinline__ void mma_tf32(float* d, const unsigned* a,
                                         unsigned b0, unsigned b1) {
  asm volatile(
      "mma.sync.aligned.m16n8k8.row.col.f32.tf32.tf32.f32 "
      "{%0,%1,%2,%3}, {%4,%5,%6,%7}, {%8,%9}, {%0,%1,%2,%3};\n"
      : "+f"(d[0]), "+f"(d[1]), "+f"(d[2]), "+f"(d[3])
      : "r"(a[0]), "r"(a[1]), "r"(a[2]), "r"(a[3]), "r"(b0), "r"(b1));
}

__global__ __launch_bounds__(224, 2) void kC(int level, int Lin, int Lout, int npairs) {
  extern __shared__ float sm[];
  float* AsH = sm;
  float* AsL = AsH + KCH_*SSTR_;
  float* BsH = AsL + KCH_*SSTR_;
  float* BsL = BsH + KCH_*SSTR_;

  const float* src; float* dst;
  switch (level) {
    case 0:  src = g_P;    dst = g_buf1; break;
    case 1:  src = g_buf1; dst = g_buf2; break;
    case 2:  src = g_buf2; dst = g_buf1; break;
    case 3:  src = g_buf1; dst = g_buf2; break;
    case 4:  src = g_buf2; dst = g_buf1; break;
    default: src = g_buf1; dst = g_buf2; break;
  }

  const int quad = blockIdx.x;        // 0..3: (rt, ct)
  const int p    = blockIdx.y;
  const int b    = blockIdx.z;
  const int tid  = threadIdx.x;

  if (p >= npairs) {                  // carry: copy last src matrix through
    const float4* Sg = reinterpret_cast<const float4*>(src + ((size_t)b*Lin + (Lin - 1))*MP2_);
    float4*       Dg = reinterpret_cast<float4*>(dst + ((size_t)b*Lout + npairs)*MP2_);
    const int q = MP2_/16;            // 3136 float4 per quarter
    for (int i = quad*q + tid; i < (quad + 1)*q; i += 224) Dg[i] = Sg[i];
    return;
  }

  const int rt = quad & 1, ct = quad >> 1;
  const float* Am = src + ((size_t)b*Lin + 2*p + 1)*MP2_;
  const float* Bm = src + ((size_t)b*Lin + 2*p    )*MP2_;
  float*       Cm = dst + ((size_t)b*Lout + p     )*MP2_;

  const int w    = tid >> 5;          // warp 0..6 -> 16-row band
  const int lane = tid & 31;
  const int g    = lane >> 2;         // groupID
  const int tig  = lane & 3;          // thread in group
  const int row0 = rt * 112;          // CTA row base
  const int col0 = ct * 112;          // CTA col base
  const int mA   = w * 16 + g;        // local A row (and +8)

  float acc[14][4];
#pragma unroll
  for (int nt = 0; nt < 14; ++nt)
#pragma unroll
    for (int j = 0; j < 4; ++j) acc[nt][j] = 0.f;

  for (int k0 = 0; k0 < NP_; k0 += KCH_) {
    __syncthreads();
    // A fill: As[k][m], k fastest across lanes (coalesced gmem, cf smem)
    for (int idx = tid; idx < KCH_*112; idx += 224) {
      const int m = idx >> 5, k = idx & 31;
      float x = Am[(size_t)(row0 + m)*NP_ + k0 + k];
      float h = __uint_as_float(f2tf32(x));
      AsH[k*SSTR_ + m] = h;
      AsL[k*SSTR_ + m] = x - h;
    }
    // B fill: Bs[k][n], n fastest (coalesced gmem, cf smem)
    for (int idx = tid; idx < KCH_*112; idx += 224) {
      const int k = idx / 112, n = idx - k*112;
      float x = Bm[(size_t)(k0 + k)*NP_ + col0 + n];
      float h = __uint_as_float(f2tf32(x));
      BsH[k*SSTR_ + n] = h;
      BsL[k*SSTR_ + n] = x - h;
    }
    __syncthreads();

#pragma unroll
    for (int ks = 0; ks < KCH_/8; ++ks) {
      const int kb = ks*8;
      unsigned aH[4], aL[4];
      const int ra0 = (kb + tig)*SSTR_;
      const int ra4 = (kb + tig + 4)*SSTR_;
      aH[0] = __float_as_uint(AsH[ra0 + mA]);
      aH[1] = __float_as_uint(AsH[ra0 + mA + 8]);
      aH[2] = __float_as_uint(AsH[ra4 + mA]);
      aH[3] = __float_as_uint(AsH[ra4 + mA + 8]);
      aL[0] = f2tf32(AsL[ra0 + mA]);
      aL[1] = f2tf32(AsL[ra0 + mA + 8]);
      aL[2] = f2tf32(AsL[ra4 + mA]);
      aL[3] = f2tf32(AsL[ra4 + mA + 8]);
#pragma unroll
      for (int nt = 0; nt < 14; ++nt) {
        const int n = nt*8 + g;
        unsigned bH0 = __float_as_uint(BsH[ra0 + n]);
        unsigned bH1 = __float_as_uint(BsH[ra4 + n]);
        unsigned bL0 = f2tf32(BsL[ra0 + n]);
        unsigned bL1 = f2tf32(BsL[ra4 + n]);
        mma_tf32(acc[nt], aH, bH0, bH1);
        mma_tf32(acc[nt], aH, bL0, bL1);
        mma_tf32(acc[nt], aL, bH0, bH1);
      }
    }
  }

  // epilogue: c0,c1 -> (row0+mA, col0+nt*8+2tig); c2,c3 -> row +8. float2 stores.
  {
    float2* Crow0 = reinterpret_cast<float2*>(Cm + (size_t)(row0 + mA    )*NP_ + col0);
    float2* Crow8 = reinterpret_cast<float2*>(Cm + (size_t)(row0 + mA + 8)*NP_ + col0);
#pragma unroll
    for (int nt = 0; nt < 14; ++nt) {
      const int cc = (nt*8 + 2*tig) >> 1;
      Crow0[cc] = make_float2(acc[nt][0], acc[nt][1]);
      Crow8[cc] = make_float2(acc[nt][2], acc[nt][3]);
    }
  }
}

// =============================================================================
// Kernel D: per-row loss/acc from final At (g_buf2[b][0], padded stride 224).
// =============================================================================
__global__ void kD() {
  __shared__ float sl[N_], sa[N_];
  const int b = blockIdx.x, n = threadIdx.x;
  const float* row = g_buf2 + (size_t)b*MP2_ + (size_t)n*NP_;
  float rs = 0.f, best = -1.f;
  int bi = 0;
  for (int m = 0; m < N_; ++m) {
    const float v = row[m];
    rs += v;
    if (v > best) { best = v; bi = m; }
  }
  const float diag = row[n];
  sl[n] = logf(rs + (float)N_ * EPS_) - logf(diag + EPS_);
  sa[n] = (bi == n) ? 1.f : 0.f;
  __syncthreads();
  if (n == 0) {
    float L = 0.f, A = 0.f;
    for (int i = 0; i < N_; ++i) { L += sl[i]; A += sa[i]; }
    g_partial[b]      = L;
    g_partial[B_ + b] = A;
  }
}

__global__ void kE(float* out, int out_size) {
  float L = 0.f, A = 0.f;
  for (int b = 0; b < B_; ++b) { L += g_partial[b]; A += g_partial[B_ + b]; }
  const float inv = 1.0f / (float)(B_ * N_);
  if (out_size > QSIZE)     out[QSIZE]     = L * inv;
  if (out_size > QSIZE + 1) out[QSIZE + 1] = A * inv;
}

// =============================================================================
extern "C" void kernel_launch(void* const* d_in, const int* in_sizes, int n_in,
                              void* d_out, int out_size) {
  const float* maps = (const float*)d_in[0];
  const float* W    = (const float*)d_in[1];
  const float* bias = (const float*)d_in[2];
  float* out = (float*)d_out;

  cudaFuncSetAttribute(kA, cudaFuncAttributeMaxDynamicSharedMemorySize, (int)SMEM_A_BYTES);
  cudaFuncSetAttribute(kB, cudaFuncAttributeMaxDynamicSharedMemorySize, (int)SMEM_B_BYTES);
  cudaFuncSetAttribute(kC, cudaFuncAttributeMaxDynamicSharedMemorySize, (int)SMEM_C_BYTES);

  kA<<<B_*N_, 128, SMEM_A_BYTES>>>(maps, W, bias, out);
  kB<<<dim3(T_ - 1, B_), 392, SMEM_B_BYTES>>>();

  // product tree: 38 -> 19 -> 10 -> 5 -> 3 -> 2 -> 1
  // {level, Lin, Lout, npairs, carry}
  const int lv[6][5] = {
    {0, 38, 19, 19, 0},
    {1, 19, 10,  9, 1},
    {2, 10,  5,  5, 0},
    {3,  5,  3,  2, 1},
    {4,  3,  2,  1, 1},
    {5,  2,  1,  1, 0},
  };
  for (int l = 0; l < 6; ++l) {
    kC<<<dim3(4, lv[l][3] + lv[l][4], B_), 224, SMEM_C_BYTES>>>(
        lv[l][0], lv[l][1], lv[l][2], lv[l][3]);
  }

  kD<<<B_, N_>>>();
  kE<<<1, 1>>>(out, out_size);
}